// round 13
// baseline (speedup 1.0000x reference)
#include <cuda_runtime.h>
#include <cuda_bf16.h>
#include <math.h>
#include <mma.h>

using namespace nvcuda;

#define NN     2048
#define EE     16384
#define BBATCH 32
#define TP2    61
#define DD     128
#define C3N    32

typedef unsigned long long u64b;

__device__ __forceinline__ void fma2(u64b& d, u64b a, u64b b) {
    asm("fma.rn.f32x2 %0, %1, %2, %0;" : "+l"(d) : "l"(a), "l"(b));
}
__device__ __forceinline__ float hsum2(u64b v) {
    float lo, hi;
    asm("mov.b64 {%0,%1}, %2;" : "=f"(lo), "=f"(hi) : "l"(v));
    return lo + hi;
}
__device__ __forceinline__ u64b expand_bf2(unsigned u) {
    unsigned lo = u << 16;
    unsigned hi = u & 0xffff0000u;
    u64b d;
    asm("mov.b64 %0, {%1, %2};" : "=l"(d) : "r"(lo), "r"(hi));
    return d;
}
__device__ __forceinline__ void add2(u64b& d, u64b a) {
    asm("add.rn.f32x2 %0, %0, %1;" : "+l"(d) : "l"(a));
}
__device__ __forceinline__ unsigned bfadd2(unsigned a, unsigned b) {
    unsigned r;
    asm("add.rn.bf16x2 %0, %1, %2;" : "=r"(r) : "r"(a), "r"(b));
    return r;
}
__device__ __forceinline__ void acc_u4(u64b* accp, uint4 b) {
    add2(accp[0], expand_bf2(b.x));
    add2(accp[1], expand_bf2(b.y));
    add2(accp[2], expand_bf2(b.z));
    add2(accp[3], expand_bf2(b.w));
}
__device__ __forceinline__ void acc_pair_u4(u64b* accp, uint4 a, uint4 b) {
    add2(accp[0], expand_bf2(bfadd2(a.x, b.x)));
    add2(accp[1], expand_bf2(bfadd2(a.y, b.y)));
    add2(accp[2], expand_bf2(bfadd2(a.z, b.z)));
    add2(accp[3], expand_bf2(bfadd2(a.w, b.w)));
}
__device__ __forceinline__ void unpack2(u64b d, float& lo, float& hi) {
    asm("mov.b64 {%0,%1}, %2;" : "=f"(lo), "=f"(hi) : "l"(d));
}
__device__ __forceinline__ unsigned pair_to_bf2(u64b d) {
    float lo, hi; unsigned r;
    asm("mov.b64 {%0,%1}, %2;" : "=f"(lo), "=f"(hi) : "l"(d));
    asm("cvt.rn.bf16x2.f32 %0, %1, %2;" : "=r"(r) : "f"(hi), "f"(lo));
    return r;
}
__device__ __forceinline__ unsigned bf2pack(float lo, float hi) {
    unsigned r;
    asm("cvt.rn.bf16x2.f32 %0, %1, %2;" : "=r"(r) : "f"(hi), "f"(lo));
    return r;
}

// ---------------- scratch ----------------
__device__ __nv_bfloat16 g_h0[NN * TP2 * C3N];
__device__ __nv_bfloat16 g_h1[NN * TP2 * DD];
__device__ __nv_bfloat16 g_t [NN * TP2 * DD];
__device__ float g_contrib[NN * 4];
__device__ float g_dinv[NN];
__device__ int   g_cnt[NN];
__device__ int   g_cur[NN];
__device__ int   g_off[NN + 1];
__device__ int   g_col[EE];

// ---------------- graph prep (multi-block, wide) ----------------
__global__ void zero_cnt_kernel() {
    int i = blockIdx.x * blockDim.x + threadIdx.x;
    if (i < NN) g_cnt[i] = 0;
}

__global__ void count_kernel(const int* __restrict__ ei) {
    int e = blockIdx.x * blockDim.x + threadIdx.x;
    if (e < EE) atomicAdd(&g_cnt[ei[EE + e]], 1);
}

__global__ void scan_kernel() {
    __shared__ int csum[256];
    const int tid = threadIdx.x;
    const int base = tid * 8;
    int local[8];
    int s = 0;
#pragma unroll
    for (int i = 0; i < 8; i++) { local[i] = s; s += g_cnt[base + i]; }
    csum[tid] = s;
    __syncthreads();
    for (int ofs = 1; ofs < 256; ofs <<= 1) {
        int v = (tid >= ofs) ? csum[tid - ofs] : 0;
        __syncthreads();
        csum[tid] += v;
        __syncthreads();
    }
    int pre = (tid == 0) ? 0 : csum[tid - 1];
#pragma unroll
    for (int i = 0; i < 8; i++) {
        int o = pre + local[i];
        g_off[base + i] = o;
        g_cur[base + i] = o;
        g_dinv[base + i] = rsqrtf((float)(g_cnt[base + i] + 1));
    }
    if (tid == 255) g_off[NN] = pre + s;
}

__global__ void fill_kernel(const int* __restrict__ ei) {
    int e = blockIdx.x * blockDim.x + threadIdx.x;
    if (e < EE) {
        int src = ei[e];
        int dst = ei[EE + e];
        int p = atomicAdd(&g_cur[dst], 1);
        g_col[p] = src;
    }
}

// ---------------- fused CNN + pos-MLP (one block per node, f32x2, 3 CTA/SM) ----------------
#define SXP_O   0
#define H1B_O   1048
#define U1_O    5160
#define H2_O    0
#define U2_O    4048
#define W3K_O   8016
#define W1E_O   13352
#define W1O_O   13544
#define W1X_O   13736
#define W2K_O   13752
#define S1_O    15800
#define B1_O    15808
#define S2_O    15816
#define B2_O    15832
#define S3_O    15848
#define B3_O    15880
#define PE_O    15912
#define HID_O   15944
#define CONV_SMEM_FLOATS 15976
#define CONV_SMEM_BYTES (CONV_SMEM_FLOATS * 4)

__global__ __launch_bounds__(256, 3) void conv_kernel(
    const float* __restrict__ x,   const float* __restrict__ pos,
    const float* __restrict__ c1w, const float* __restrict__ c1b,
    const float* __restrict__ g1,  const float* __restrict__ b1,
    const float* __restrict__ c2w, const float* __restrict__ c2b,
    const float* __restrict__ g2,  const float* __restrict__ b2,
    const float* __restrict__ c3w, const float* __restrict__ c3b,
    const float* __restrict__ g3,  const float* __restrict__ b3,
    const float* __restrict__ pw1, const float* __restrict__ pb1,
    const float* __restrict__ pw2, const float* __restrict__ pb2,
    __nv_bfloat16* __restrict__ out)
{
    extern __shared__ float sm[];
    unsigned* smu = (unsigned*)sm;
    const int n = blockIdx.x;
    const int tid = threadIdx.x;
    const float rs = rsqrtf(1.0f + 1e-5f);
    const float dvn = g_dinv[n];

    for (int i = tid; i < 96; i += 256) {
        int c = i / 12, m = i % 12;
        sm[W1E_O + 2 * i]     = c1w[c * 25 + 2 * m];
        sm[W1E_O + 2 * i + 1] = c1w[c * 25 + 2 * m + 1];
    }
    for (int i = tid; i < 96; i += 256) {
        int c = i / 12, m = i % 12;
        sm[W1O_O + 2 * i]     = c1w[c * 25 + 2 * m + 1];
        sm[W1O_O + 2 * i + 1] = c1w[c * 25 + 2 * m + 2];
    }
    if (tid < 8)  sm[W1X_O + tid] = c1w[tid * 25];
    else if (tid < 16) sm[W1X_O + tid] = c1w[(tid - 8) * 25 + 24];
    for (int i = tid; i < 512; i += 256) {
        int ci = i >> 6, m = (i >> 3) & 7, q = i & 7;
        int base = q * 120 + ci * 15 + 2 * m;
        float4 v;
        v.x = c2w[base];
        v.y = (2 * m + 1 < 15) ? c2w[base + 1] : 0.f;
        v.z = c2w[base + 960];
        v.w = (2 * m + 1 < 15) ? c2w[base + 961] : 0.f;
        *(float4*)&sm[W2K_O + 4 * i] = v;
    }
    if (tid < 8) {
        float s = g1[tid] * rs; sm[S1_O + tid] = s; sm[B1_O + tid] = c1b[tid] * s + b1[tid];
    } else if (tid >= 32 && tid < 48) {
        int c = tid - 32; float s = g2[c] * rs; sm[S2_O + c] = s; sm[B2_O + c] = c2b[c] * s + b2[c];
    } else if (tid >= 64 && tid < 96) {
        int c = tid - 64; float s = g3[c] * rs; sm[S3_O + c] = s; sm[B3_O + c] = c3b[c] * s + b3[c];
    }
    if (tid >= 128 && tid < 160) {
        int c = tid - 128;
        float p0 = pos[n * 3 + 0], p1 = pos[n * 3 + 1], p2 = pos[n * 3 + 2];
        float h = p0 * pw1[c] + p1 * pw1[32 + c] + p2 * pw1[64 + c] + pb1[c];
        sm[HID_O + c] = fmaxf(h, 0.f);
    }
    for (int i = tid; i < 1024; i += 256) sm[SXP_O + 12 + i] = x[(size_t)n * 1024 + i];
    if (tid < 12) { sm[SXP_O + tid] = 0.f; sm[SXP_O + 1036 + tid] = 0.f; }
    __syncthreads();

    if (tid < 32) {
        float s = pb2[tid];
#pragma unroll
        for (int j = 0; j < 32; j++) s += sm[HID_O + j] * pw2[j * 32 + tid];
        sm[PE_O + tid] = s;
    }

    // conv1 (1->8, K=25) + BN + relu, write bf16 h1b
    {
        const int t0 = tid * 4;
        union UU { float4 q[7]; u64b p[14]; float f[28]; } uu;
#pragma unroll
        for (int i = 0; i < 7; i++) uu.q[i] = *(const float4*)&sm[SXP_O + t0 + 4 * i];
        const u64b* w1e = (const u64b*)&sm[W1E_O];
        const u64b* w1o = (const u64b*)&sm[W1O_O];
#pragma unroll
        for (int c = 0; c < 8; c++) {
            u64b a0 = 0, a1 = 0, a2 = 0, a3 = 0;
#pragma unroll
            for (int m = 0; m < 12; m++) {
                u64b we = w1e[c * 12 + m];
                fma2(a0, we, uu.p[m]);
                fma2(a2, we, uu.p[m + 1]);
                u64b wo = w1o[c * 12 + m];
                fma2(a1, wo, uu.p[m + 1]);
                fma2(a3, wo, uu.p[m + 2]);
            }
            float w0 = sm[W1X_O + c], w24 = sm[W1X_O + 8 + c];
            float v0 = hsum2(a0) + w24 * uu.f[24];
            float v1 = hsum2(a1) + w0  * uu.f[1];
            float v2 = hsum2(a2) + w24 * uu.f[26];
            float v3 = hsum2(a3) + w0  * uu.f[3];
            float s = sm[S1_O + c], B = sm[B1_O + c];
            float o0 = fmaxf(v0 * s + B, 0.f);
            float o1 = fmaxf(v1 * s + B, 0.f);
            float o2 = fmaxf(v2 * s + B, 0.f);
            float o3 = fmaxf(v3 * s + B, 0.f);
            uint2 pk;
            pk.x = bf2pack(o0, o1);
            pk.y = bf2pack(o2, o3);
            *(uint2*)&smu[H1B_O + c * 514 + (t0 >> 1)] = pk;
        }
    }
    __syncthreads();

    // pool1: u1 (f32) from bf16 h1b
    for (int c = 0; c < 8; c++) {
        const unsigned* hb = &smu[H1B_O + c * 514];
        for (int j2 = tid; j2 < 510; j2 += 256) {
            unsigned a = hb[j2], b = hb[j2 + 1], d = hb[j2 + 2];
            float a0 = __uint_as_float(a << 16), a1 = __uint_as_float(a & 0xffff0000u);
            float b0 = __uint_as_float(b << 16), b1 = __uint_as_float(b & 0xffff0000u);
            float d0 = __uint_as_float(d << 16);
            float mid = a1 + b0 + b1;
            sm[U1_O + c * 1024 + 2 * j2]     = 0.25f * (a0 + mid);
            sm[U1_O + c * 1024 + 2 * j2 + 1] = 0.25f * (mid + d0);
        }
    }
    __syncthreads();

    // conv2 (8->16, K=15 padded 16) fused pool4 + BN + relu -> h2 (f32)
    {
        const int q = tid & 7, tpq = tid >> 3;
        u64b accL[8], accH[8];
#pragma unroll
        for (int it = 0; it < 8; it++) { accL[it] = 0; accH[it] = 0; }
#pragma unroll
        for (int ci = 0; ci < 8; ci++) {
            union WU { float4 v; u64b p[2]; } wv[8];
#pragma unroll
            for (int m = 0; m < 8; m++)
                wv[m].v = *(const float4*)&sm[W2K_O + 4 * ((ci * 8 + m) * 8 + q)];
#pragma unroll
            for (int it = 0; it < 8; it++) {
                int tp = tpq + 32 * it;
                if (tp < 252) {
                    union UB { float4 v[4]; u64b p[8]; } ub;
                    const float4* up = (const float4*)&sm[U1_O + ci * 1024 + 4 * tp];
#pragma unroll
                    for (int i = 0; i < 4; i++) ub.v[i] = up[i];
#pragma unroll
                    for (int m = 0; m < 8; m++) {
                        fma2(accL[it], wv[m].p[0], ub.p[m]);
                        fma2(accH[it], wv[m].p[1], ub.p[m]);
                    }
                }
            }
        }
        float sL = sm[S2_O + q], BL = sm[B2_O + q];
        float sH = sm[S2_O + q + 8], BH = sm[B2_O + q + 8];
#pragma unroll
        for (int it = 0; it < 8; it++) {
            int tp = tpq + 32 * it;
            if (tp < 252) {
                sm[H2_O + q * 253 + tp]       = fmaxf(hsum2(accL[it]) * sL + BL, 0.f);
                sm[H2_O + (q + 8) * 253 + tp] = fmaxf(hsum2(accH[it]) * sH + BH, 0.f);
            }
        }
    }
    __syncthreads();

    // pool2 (u2) + late load of conv3 weights into dead u1 space
    for (int i = tid; i < 1024; i += 256) {
        int ci = i >> 6, m = (i >> 4) & 3, q = i & 15;
        int base = q * 112 + ci * 7 + 2 * m;
        float4 v;
        v.x = c3w[base];
        v.y = (2 * m + 1 < 7) ? c3w[base + 1] : 0.f;
        v.z = c3w[base + 1792];
        v.w = (2 * m + 1 < 7) ? c3w[base + 1793] : 0.f;
        *(float4*)&sm[W3K_O + 4 * i] = v;
    }
    for (int j = tid; j < 16 * 248; j += 256) {
        int c = j / 248, jj = j % 248;
        const float* hr = &sm[H2_O + c * 253 + jj];
        sm[U2_O + c * 248 + jj] = 0.25f * (hr[0] + hr[1] + hr[2] + hr[3]);
    }
    __syncthreads();

    // conv3 (16->32, K=7 padded 8) fused pool4 + pe, write bf16 pre-scaled by dinv[n]
    {
        const int q = tid & 15, tpq = tid >> 4;
        u64b accL[4], accH[4];
#pragma unroll
        for (int it = 0; it < 4; it++) { accL[it] = 0; accH[it] = 0; }
#pragma unroll
        for (int ci = 0; ci < 16; ci++) {
            union WU { float4 v; u64b p[2]; } wv[4];
#pragma unroll
            for (int m = 0; m < 4; m++)
                wv[m].v = *(const float4*)&sm[W3K_O + 4 * ((ci * 4 + m) * 16 + q)];
#pragma unroll
            for (int it = 0; it < 4; it++) {
                int tp = tpq + 16 * it;
                if (tp < 61) {
                    union UB { float4 v[2]; u64b p[4]; } ub;
                    const float4* up = (const float4*)&sm[U2_O + ci * 248 + 4 * tp];
                    ub.v[0] = up[0]; ub.v[1] = up[1];
#pragma unroll
                    for (int m = 0; m < 4; m++) {
                        fma2(accL[it], wv[m].p[0], ub.p[m]);
                        fma2(accH[it], wv[m].p[1], ub.p[m]);
                    }
                }
            }
        }
        float sL = sm[S3_O + q], BL = sm[B3_O + q], peL = sm[PE_O + q];
        float sH = sm[S3_O + q + 16], BH = sm[B3_O + q + 16], peH = sm[PE_O + q + 16];
#pragma unroll
        for (int it = 0; it < 4; it++) {
            int tp = tpq + 16 * it;
            if (tp < 61) {
                size_t base = ((size_t)n * 61 + tp) * 32;
                out[base + q]      = __float2bfloat16((fmaxf(hsum2(accL[it]) * sL + BL, 0.f) + peL) * dvn);
                out[base + q + 16] = __float2bfloat16((fmaxf(hsum2(accH[it]) * sH + BH, 0.f) + peH) * dvn);
            }
        }
    }
}

// ---------------- layer-1 fused GCN: gather + bf16 wmma GEMM (2 nodes/block) ----------------
// Input h pre-scaled by dinv[src]; gather is a pure sum.
// Output: relu((s@W)*dinv+b)*dinv (pre-scaled for next layer).
__global__ __launch_bounds__(256, 2) void gcn1_kernel(
    const __nv_bfloat16* __restrict__ h, const float* __restrict__ W,
    const float* __restrict__ bias, __nv_bfloat16* __restrict__ out)
{
    constexpr int K = 32;
    constexpr int LDA = K + 8;
    constexpr int LDW = 136;
    constexpr int LDC = 132;
    constexpr int V8 = TP2 * K / 8;   // 244
    extern __shared__ char sgc[];
    __nv_bfloat16* ws = (__nv_bfloat16*)sgc;
    __nv_bfloat16* as = ws + K * LDW;
    float* cs = (float*)sgc;
    __shared__ float bs[128];

    const int tid = threadIdx.x;
    const int bid = blockIdx.x;

    if (tid < 128) bs[tid] = bias[tid];
    for (int i = tid; i < K * 32; i += 256) {
        int k = i >> 5, c4 = i & 31;
        float4 v = *(const float4*)&W[k * 128 + c4 * 4];
        __nv_bfloat16* p = &ws[k * LDW + c4 * 4];
        p[0] = __float2bfloat16(v.x); p[1] = __float2bfloat16(v.y);
        p[2] = __float2bfloat16(v.z); p[3] = __float2bfloat16(v.w);
    }
    for (int i = tid; i < 6 * (K / 8); i += 256) {
        int r = 122 + i / (K / 8), c8 = i % (K / 8);
        *(uint4*)&as[r * LDA + c8 * 8] = make_uint4(0, 0, 0, 0);
    }

#pragma unroll 1
    for (int nh = 0; nh < 2; nh++) {
        const int n = 2 * bid + nh;
        const uint4* hn = (const uint4*)(h + (size_t)n * (TP2 * K));
        u64b accp[4];
        if (tid < V8) {
            uint4 b = hn[tid];
            accp[0] = expand_bf2(b.x);
            accp[1] = expand_bf2(b.y);
            accp[2] = expand_bf2(b.z);
            accp[3] = expand_bf2(b.w);
        }
        const int jb = g_off[n], je = g_off[n + 1];
        int e = jb;
        for (; e + 4 <= je; e += 4) {
            const uint4* p0 = (const uint4*)(h + (size_t)g_col[e]     * (TP2 * K));
            const uint4* p1 = (const uint4*)(h + (size_t)g_col[e + 1] * (TP2 * K));
            const uint4* p2 = (const uint4*)(h + (size_t)g_col[e + 2] * (TP2 * K));
            const uint4* p3 = (const uint4*)(h + (size_t)g_col[e + 3] * (TP2 * K));
            if (tid < V8) {
                uint4 b0 = p0[tid], b1 = p1[tid], b2 = p2[tid], b3 = p3[tid];
                acc_pair_u4(accp, b0, b1);
                acc_pair_u4(accp, b2, b3);
            }
        }
        for (; e + 2 <= je; e += 2) {
            const uint4* p0 = (const uint4*)(h + (size_t)g_col[e]     * (TP2 * K));
            const uint4* p1 = (const uint4*)(h + (size_t)g_col[e + 1] * (TP2 * K));
            if (tid < V8) {
                uint4 b0 = p0[tid], b1 = p1[tid];
                acc_pair_u4(accp, b0, b1);
            }
        }
        if (e < je) {
            const uint4* p0 = (const uint4*)(h + (size_t)g_col[e] * (TP2 * K));
            if (tid < V8) acc_u4(accp, p0[tid]);
        }
        if (tid < V8) {
            int r = nh * TP2 + tid / (K / 8), c8 = tid % (K / 8);
            uint4 o;
            o.x = pair_to_bf2(accp[0]);
            o.y = pair_to_bf2(accp[1]);
            o.z = pair_to_bf2(accp[2]);
            o.w = pair_to_bf2(accp[3]);
            *(uint4*)&as[r * LDA + c8 * 8] = o;
        }
    }
    __syncthreads();

    const int wid = tid >> 5;
    const int wr = wid & 3;
    const int wc = wid >> 2;
    wmma::fragment<wmma::accumulator, 16, 16, 16, float> cf[2][4];
#pragma unroll
    for (int i = 0; i < 2; i++)
#pragma unroll
        for (int j = 0; j < 4; j++) wmma::fill_fragment(cf[i][j], 0.f);

#pragma unroll
    for (int k0 = 0; k0 < K; k0 += 16) {
        wmma::fragment<wmma::matrix_a, 16, 16, 16, __nv_bfloat16, wmma::row_major> af[2];
#pragma unroll
        for (int i = 0; i < 2; i++)
            wmma::load_matrix_sync(af[i], as + (wr * 32 + i * 16) * LDA + k0, LDA);
        wmma::fragment<wmma::matrix_b, 16, 16, 16, __nv_bfloat16, wmma::row_major> bf[4];
#pragma unroll
        for (int j = 0; j < 4; j++)
            wmma::load_matrix_sync(bf[j], ws + k0 * LDW + wc * 64 + j * 16, LDW);
#pragma unroll
        for (int i = 0; i < 2; i++)
#pragma unroll
            for (int j = 0; j < 4; j++)
                wmma::mma_sync(cf[i][j], af[i], bf[j], cf[i][j]);
    }
    __syncthreads();
#pragma unroll
    for (int i = 0; i < 2; i++)
#pragma unroll
        for (int j = 0; j < 4; j++)
            wmma::store_matrix_sync(cs + (wr * 32 + i * 16) * LDC + wc * 64 + j * 16,
                                    cf[i][j], LDC, wmma::mem_row_major);
    __syncthreads();

    for (int idx = tid; idx < 128 * 64; idx += 256) {
        int r = idx >> 6, c2 = idx & 63;
        if (r < 122) {
            int nh = (r >= TP2) ? 1 : 0;
            int n = 2 * bid + nh;
            int t = r - TP2 * nh;
            float dv = g_dinv[n];
            float v0 = fmaxf(cs[r * LDC + 2 * c2]     * dv + bs[2 * c2], 0.f) * dv;
            float v1 = fmaxf(cs[r * LDC + 2 * c2 + 1] * dv + bs[2 * c2 + 1], 0.f) * dv;
            ((__nv_bfloat162*)out)[(size_t)(n * TP2 + t) * 64 + c2] =
                __floats2bfloat162_rn(v0, v1);
        }
    }
}

// ---------------- layer-2 GEMM: t = h1 @ W2 (no gather; rows contiguous) ----------------
__global__ __launch_bounds__(256, 2) void gemm_t_kernel(
    const __nv_bfloat16* __restrict__ h, const float* __restrict__ W,
    __nv_bfloat16* __restrict__ t)
{
    constexpr int K = 128;
    constexpr int LDA = 136;
    constexpr int LDW = 136;
    constexpr int LDC = 132;
    extern __shared__ char sgc[];
    __nv_bfloat16* ws = (__nv_bfloat16*)sgc;      // K*LDW
    __nv_bfloat16* as = ws + K * LDW;              // 128*LDA
    float* cs = (float*)sgc;                        // C reuse

    const int tid = threadIdx.x;
    const size_t row0 = (size_t)blockIdx.x * 128;

    for (int i = tid; i < K * 32; i += 256) {
        int k = i >> 5, c4 = i & 31;
        float4 v = *(const float4*)&W[k * 128 + c4 * 4];
        __nv_bfloat16* p = &ws[k * LDW + c4 * 4];
        p[0] = __float2bfloat16(v.x); p[1] = __float2bfloat16(v.y);
        p[2] = __float2bfloat16(v.z); p[3] = __float2bfloat16(v.w);
    }
    const uint4* hr = (const uint4*)(h + row0 * K);
    for (int i = tid; i < 2048; i += 256) {
        int r = i >> 4, c8 = i & 15;
        *(uint4*)&as[r * LDA + c8 * 8] = hr[i];
    }
    __syncthreads();

    const int wid = tid >> 5;
    const int wr = wid & 3;
    const int wc = wid >> 2;
    wmma::fragment<wmma::accumulator, 16, 16, 16, float> cf[2][4];
#pragma unroll
    for (int i = 0; i < 2; i++)
#pragma unroll
        for (int j = 0; j < 4; j++) wmma::fill_fragment(cf[i][j], 0.f);

#pragma unroll
    for (int k0 = 0; k0 < K; k0 += 16) {
        wmma::fragment<wmma::matrix_a, 16, 16, 16, __nv_bfloat16, wmma::row_major> af[2];
#pragma unroll
        for (int i = 0; i < 2; i++)
            wmma::load_matrix_sync(af[i], as + (wr * 32 + i * 16) * LDA + k0, LDA);
        wmma::fragment<wmma::matrix_b, 16, 16, 16, __nv_bfloat16, wmma::row_major> bf[4];
#pragma unroll
        for (int j = 0; j < 4; j++)
            wmma::load_matrix_sync(bf[j], ws + k0 * LDW + wc * 64 + j * 16, LDW);
#pragma unroll
        for (int i = 0; i < 2; i++)
#pragma unroll
            for (int j = 0; j < 4; j++)
                wmma::mma_sync(cf[i][j], af[i], bf[j], cf[i][j]);
    }
    __syncthreads();
#pragma unroll
    for (int i = 0; i < 2; i++)
#pragma unroll
        for (int j = 0; j < 4; j++)
            wmma::store_matrix_sync(cs + (wr * 32 + i * 16) * LDC + wc * 64 + j * 16,
                                    cf[i][j], LDC, wmma::mem_row_major);
    __syncthreads();

    for (int idx = tid; idx < 128 * 64; idx += 256) {
        int r = idx >> 6, c2 = idx & 63;
        ((__nv_bfloat162*)t)[(row0 + r) * 64 + c2] =
            __floats2bfloat162_rn(cs[r * LDC + 2 * c2], cs[r * LDC + 2 * c2 + 1]);
    }
}

// ---------------- layer-2 gather + epilogue + contrib (high-occupancy) ----------------
// s = Σ t[self+neighbors]; v = relu(s*dinv + bias); contrib[n] = Σ v·dw
__global__ __launch_bounds__(256, 3) void gather_contrib_kernel(
    const __nv_bfloat16* __restrict__ t,
    const float* __restrict__ bias, const float* __restrict__ dw)
{
    constexpr int V8 = TP2 * DD / 8;   // 976
    const int n = blockIdx.x, tid = threadIdx.x;
    __shared__ float bsm[128];
    __shared__ float red[8][4];
    if (tid < 128) bsm[tid] = bias[tid];

    u64b accp[4][4];
    const uint4* tn = (const uint4*)(t + (size_t)n * (TP2 * DD));
#pragma unroll
    for (int v = 0; v < 4; v++) {
        int i = tid + v * 256;
        if (i < V8) {
            uint4 b = tn[i];
            accp[v][0] = expand_bf2(b.x);
            accp[v][1] = expand_bf2(b.y);
            accp[v][2] = expand_bf2(b.z);
            accp[v][3] = expand_bf2(b.w);
        }
    }
    const int jb = g_off[n], je = g_off[n + 1];
    for (int e = jb; e < je; e++) {
        const uint4* ts = (const uint4*)(t + (size_t)g_col[e] * (TP2 * DD));
        uint4 b[4];
#pragma unroll
        for (int v = 0; v < 4; v++) {
            int i = tid + v * 256;
            if (i < V8) b[v] = ts[i];
        }
#pragma unroll
        for (int v = 0; v < 4; v++) {
            int i = tid + v * 256;
            if (i < V8) acc_u4(accp[v], b[v]);
        }
    }
    __syncthreads();   // bsm ready

    const float dv = g_dinv[n];
    float a0 = 0.f, a1 = 0.f, a2 = 0.f, a3 = 0.f;
#pragma unroll
    for (int v = 0; v < 4; v++) {
        int i = tid + v * 256;
        if (i < V8) {
            int tt = i >> 4, d0 = (i & 15) * 8;
            float f[8];
            unpack2(accp[v][0], f[0], f[1]);
            unpack2(accp[v][1], f[2], f[3]);
            unpack2(accp[v][2], f[4], f[5]);
            unpack2(accp[v][3], f[6], f[7]);
#pragma unroll
            for (int j = 0; j < 8; j++) {
                float val = fmaxf(f[j] * dv + bsm[d0 + j], 0.f);
                const float4 w = *(const float4*)&dw[(size_t)((d0 + j) * TP2 + tt) * 4];
                a0 += val * w.x; a1 += val * w.y; a2 += val * w.z; a3 += val * w.w;
            }
        }
    }
#pragma unroll
    for (int o = 16; o > 0; o >>= 1) {
        a0 += __shfl_down_sync(0xffffffff, a0, o);
        a1 += __shfl_down_sync(0xffffffff, a1, o);
        a2 += __shfl_down_sync(0xffffffff, a2, o);
        a3 += __shfl_down_sync(0xffffffff, a3, o);
    }
    const int wid = tid >> 5;
    if ((tid & 31) == 0) {
        red[wid][0] = a0; red[wid][1] = a1; red[wid][2] = a2; red[wid][3] = a3;
    }
    __syncthreads();
    if (tid < 4) {
        float s = 0.f;
#pragma unroll
        for (int w = 0; w < 8; w++) s += red[w][tid];
        g_contrib[n * 4 + tid] = s;
    }
}

// ---------------- batch pooling + bias + log_softmax ----------------
__global__ __launch_bounds__(256) void final_kernel(
    const int* __restrict__ batch, const float* __restrict__ db,
    float* __restrict__ out)
{
    const int b = blockIdx.x, tid = threadIdx.x;
    float a0 = 0.f, a1 = 0.f, a2 = 0.f, a3 = 0.f;
    int c = 0;
    for (int n = tid; n < NN; n += 256) {
        if (batch[n] == b) {
            const float4 v = *(const float4*)&g_contrib[n * 4];
            a0 += v.x; a1 += v.y; a2 += v.z; a3 += v.w;
            c++;
        }
    }
    __shared__ float r0[256], r1[256], r2[256], r3[256];
    __shared__ int rc[256];
    r0[tid] = a0; r1[tid] = a1; r2[tid] = a2; r3[tid] = a3; rc[tid] = c;
    __syncthreads();
    for (int s = 128; s > 0; s >>= 1) {
        if (tid < s) {
            r0[tid] += r0[tid + s]; r1[tid] += r1[tid + s];
            r2[tid] += r2[tid + s]; r3[tid] += r3[tid + s];
            rc[tid] += rc[tid + s];
        }
        __syncthreads();
    }
    if (tid == 0) {
        float cc = fmaxf((float)rc[0], 1.f);
        float l0 = r0[0] / cc + db[0];
        float l1 = r1[0] / cc + db[1];
        float l2 = r2[0] / cc + db[2];
        float l3 = r3[0] / cc + db[3];
        float m = fmaxf(fmaxf(l0, l1), fmaxf(l2, l3));
        float sum = expf(l0 - m) + expf(l1 - m) + expf(l2 - m) + expf(l3 - m);
        float ls = logf(sum);
        out[b * 4 + 0] = l0 - m - ls;
        out[b * 4 + 1] = l1 - m - ls;
        out[b * 4 + 2] = l2 - m - ls;
        out[b * 4 + 3] = l3 - m - ls;
    }
}

// ---------------- launch ----------------
extern "C" void kernel_launch(void* const* d_in, const int* in_sizes, int n_in,
                              void* d_out, int out_size)
{
    const float* x   = (const float*)d_in[0];
    const float* pos = (const float*)d_in[1];
    const float* c1w = (const float*)d_in[2];
    const float* c1b = (const float*)d_in[3];
    const float* bg1 = (const float*)d_in[4];
    const float* bb1 = (const float*)d_in[5];
    const float* c2w = (const float*)d_in[6];
    const float* c2b = (const float*)d_in[7];
    const float* bg2 = (const float*)d_in[8];
    const float* bb2 = (const float*)d_in[9];
    const float* c3w = (const float*)d_in[10];
    const float* c3b = (const float*)d_in[11];
    const float* bg3 = (const float*)d_in[12];
    const float* bb3 = (const float*)d_in[13];
    const float* pw1 = (const float*)d_in[14];
    const float* pb1 = (const float*)d_in[15];
    const float* pw2 = (const float*)d_in[16];
    const float* pb2 = (const float*)d_in[17];
    const float* gw1 = (const float*)d_in[18];
    const float* gb1 = (const float*)d_in[19];
    const float* gw2 = (const float*)d_in[20];
    const float* gb2 = (const float*)d_in[21];
    const float* dw  = (const float*)d_in[22];
    const float* db  = (const float*)d_in[23];
    const int*   ei  = (const int*)d_in[24];
    const int*   bat = (const int*)d_in[25];
    float* out = (float*)d_out;

    const int g1_smem = 128 * 132 * 4;                    // 67584
    const int gt_smem = (128 * 136 + 128 * 136) * 2;      // 69632

    cudaFuncSetAttribute(conv_kernel, cudaFuncAttributeMaxDynamicSharedMemorySize, CONV_SMEM_BYTES);
    cudaFuncSetAttribute(gcn1_kernel,   cudaFuncAttributeMaxDynamicSharedMemorySize, g1_smem);
    cudaFuncSetAttribute(gemm_t_kernel, cudaFuncAttributeMaxDynamicSharedMemorySize, gt_smem);

    __nv_bfloat16 *h0, *h1, *tb;
    cudaGetSymbolAddress((void**)&h0, g_h0);
    cudaGetSymbolAddress((void**)&h1, g_h1);
    cudaGetSymbolAddress((void**)&tb, g_t);

    zero_cnt_kernel<<<8, 256>>>();
    count_kernel<<<64, 256>>>(ei);
    scan_kernel<<<1, 256>>>();
    fill_kernel<<<64, 256>>>(ei);

    conv_kernel<<<NN, 256, CONV_SMEM_BYTES>>>(
        x, pos, c1w, c1b, bg1, bb1, c2w, c2b, bg2, bb2,
        c3w, c3b, bg3, bb3, pw1, pb1, pw2, pb2, h0);

    gcn1_kernel<<<NN / 2, 256, g1_smem>>>(h0, gw1, gb1, h1);

    gemm_t_kernel<<<(NN * TP2) / 128, 256, gt_smem>>>(h1, gw2, tb);
    gather_contrib_kernel<<<NN, 256>>>(tb, gb2, dw);

    final_kernel<<<BBATCH, 256>>>(bat, db, out);
}

// round 14
// speedup vs baseline: 1.2499x; 1.2499x over previous
#include <cuda_runtime.h>
#include <cuda_bf16.h>
#include <math.h>
#include <mma.h>

using namespace nvcuda;

#define NN     2048
#define EE     16384
#define BBATCH 32
#define TP2    61
#define DD     128
#define C3N    32

typedef unsigned long long u64b;

__device__ __forceinline__ void fma2(u64b& d, u64b a, u64b b) {
    asm("fma.rn.f32x2 %0, %1, %2, %0;" : "+l"(d) : "l"(a), "l"(b));
}
__device__ __forceinline__ float hsum2(u64b v) {
    float lo, hi;
    asm("mov.b64 {%0,%1}, %2;" : "=f"(lo), "=f"(hi) : "l"(v));
    return lo + hi;
}
__device__ __forceinline__ u64b expand_bf2(unsigned u) {
    unsigned lo = u << 16;
    unsigned hi = u & 0xffff0000u;
    u64b d;
    asm("mov.b64 %0, {%1, %2};" : "=l"(d) : "r"(lo), "r"(hi));
    return d;
}
__device__ __forceinline__ void add2(u64b& d, u64b a) {
    asm("add.rn.f32x2 %0, %0, %1;" : "+l"(d) : "l"(a));
}
__device__ __forceinline__ unsigned bfadd2(unsigned a, unsigned b) {
    unsigned r;
    asm("add.rn.bf16x2 %0, %1, %2;" : "=r"(r) : "r"(a), "r"(b));
    return r;
}
__device__ __forceinline__ void acc_u4(u64b* accp, uint4 b) {
    add2(accp[0], expand_bf2(b.x));
    add2(accp[1], expand_bf2(b.y));
    add2(accp[2], expand_bf2(b.z));
    add2(accp[3], expand_bf2(b.w));
}
__device__ __forceinline__ void acc_pair_u4(u64b* accp, uint4 a, uint4 b) {
    add2(accp[0], expand_bf2(bfadd2(a.x, b.x)));
    add2(accp[1], expand_bf2(bfadd2(a.y, b.y)));
    add2(accp[2], expand_bf2(bfadd2(a.z, b.z)));
    add2(accp[3], expand_bf2(bfadd2(a.w, b.w)));
}
__device__ __forceinline__ unsigned pair_to_bf2(u64b d) {
    float lo, hi; unsigned r;
    asm("mov.b64 {%0,%1}, %2;" : "=f"(lo), "=f"(hi) : "l"(d));
    asm("cvt.rn.bf16x2.f32 %0, %1, %2;" : "=r"(r) : "f"(hi), "f"(lo));
    return r;
}
__device__ __forceinline__ unsigned bf2pack(float lo, float hi) {
    unsigned r;
    asm("cvt.rn.bf16x2.f32 %0, %1, %2;" : "=r"(r) : "f"(hi), "f"(lo));
    return r;
}

// ---------------- scratch ----------------
__device__ __nv_bfloat16 g_h0[NN * TP2 * C3N];
__device__ __nv_bfloat16 g_h1[NN * TP2 * DD];
__device__ float g_dwt[TP2 * DD * 4];     // dw transposed: [(t*128+d)*4 + j]
__device__ float g_contrib[NN * 4];
__device__ float g_dinv[NN];
__device__ int   g_cnt[NN];
__device__ int   g_cur[NN];
__device__ int   g_off[NN + 1];
__device__ int   g_col[EE];

// ---------------- graph prep (multi-block, wide) ----------------
__global__ void zero_cnt_kernel() {
    int i = blockIdx.x * blockDim.x + threadIdx.x;
    if (i < NN) g_cnt[i] = 0;
}

__global__ void count_kernel(const int* __restrict__ ei) {
    int e = blockIdx.x * blockDim.x + threadIdx.x;
    if (e < EE) atomicAdd(&g_cnt[ei[EE + e]], 1);
}

__global__ void scan_kernel() {
    __shared__ int csum[256];
    const int tid = threadIdx.x;
    const int base = tid * 8;
    int local[8];
    int s = 0;
#pragma unroll
    for (int i = 0; i < 8; i++) { local[i] = s; s += g_cnt[base + i]; }
    csum[tid] = s;
    __syncthreads();
    for (int ofs = 1; ofs < 256; ofs <<= 1) {
        int v = (tid >= ofs) ? csum[tid - ofs] : 0;
        __syncthreads();
        csum[tid] += v;
        __syncthreads();
    }
    int pre = (tid == 0) ? 0 : csum[tid - 1];
#pragma unroll
    for (int i = 0; i < 8; i++) {
        int o = pre + local[i];
        g_off[base + i] = o;
        g_cur[base + i] = o;
        g_dinv[base + i] = rsqrtf((float)(g_cnt[base + i] + 1));
    }
    if (tid == 255) g_off[NN] = pre + s;
}

__global__ void fill_kernel(const int* __restrict__ ei) {
    int e = blockIdx.x * blockDim.x + threadIdx.x;
    if (e < EE) {
        int src = ei[e];
        int dst = ei[EE + e];
        int p = atomicAdd(&g_cur[dst], 1);
        g_col[p] = src;
    }
}

// transpose dense weights: dwt[(t*128+d)] = dw[(d*61+t)] (float4 rows)
__global__ void dwt_kernel(const float* __restrict__ dw) {
    int i = blockIdx.x * blockDim.x + threadIdx.x;   // i = t*128 + d
    if (i < TP2 * DD) {
        int t = i >> 7, d = i & 127;
        *(float4*)&g_dwt[i * 4] = *(const float4*)&dw[(size_t)(d * TP2 + t) * 4];
    }
}

// ---------------- fused CNN + pos-MLP (one block per node, f32x2, 3 CTA/SM) ----------------
#define SXP_O   0
#define H1B_O   1048
#define U1_O    5160
#define H2_O    0
#define U2_O    4048
#define W3K_O   8016
#define W1E_O   13352
#define W1O_O   13544
#define W1X_O   13736
#define W2K_O   13752
#define S1_O    15800
#define B1_O    15808
#define S2_O    15816
#define B2_O    15832
#define S3_O    15848
#define B3_O    15880
#define PE_O    15912
#define HID_O   15944
#define CONV_SMEM_FLOATS 15976
#define CONV_SMEM_BYTES (CONV_SMEM_FLOATS * 4)

__global__ __launch_bounds__(256, 3) void conv_kernel(
    const float* __restrict__ x,   const float* __restrict__ pos,
    const float* __restrict__ c1w, const float* __restrict__ c1b,
    const float* __restrict__ g1,  const float* __restrict__ b1,
    const float* __restrict__ c2w, const float* __restrict__ c2b,
    const float* __restrict__ g2,  const float* __restrict__ b2,
    const float* __restrict__ c3w, const float* __restrict__ c3b,
    const float* __restrict__ g3,  const float* __restrict__ b3,
    const float* __restrict__ pw1, const float* __restrict__ pb1,
    const float* __restrict__ pw2, const float* __restrict__ pb2,
    __nv_bfloat16* __restrict__ out)
{
    extern __shared__ float sm[];
    unsigned* smu = (unsigned*)sm;
    const int n = blockIdx.x;
    const int tid = threadIdx.x;
    const float rs = rsqrtf(1.0f + 1e-5f);
    const float dvn = g_dinv[n];

    for (int i = tid; i < 96; i += 256) {
        int c = i / 12, m = i % 12;
        sm[W1E_O + 2 * i]     = c1w[c * 25 + 2 * m];
        sm[W1E_O + 2 * i + 1] = c1w[c * 25 + 2 * m + 1];
    }
    for (int i = tid; i < 96; i += 256) {
        int c = i / 12, m = i % 12;
        sm[W1O_O + 2 * i]     = c1w[c * 25 + 2 * m + 1];
        sm[W1O_O + 2 * i + 1] = c1w[c * 25 + 2 * m + 2];
    }
    if (tid < 8)  sm[W1X_O + tid] = c1w[tid * 25];
    else if (tid < 16) sm[W1X_O + tid] = c1w[(tid - 8) * 25 + 24];
    for (int i = tid; i < 512; i += 256) {
        int ci = i >> 6, m = (i >> 3) & 7, q = i & 7;
        int base = q * 120 + ci * 15 + 2 * m;
        float4 v;
        v.x = c2w[base];
        v.y = (2 * m + 1 < 15) ? c2w[base + 1] : 0.f;
        v.z = c2w[base + 960];
        v.w = (2 * m + 1 < 15) ? c2w[base + 961] : 0.f;
        *(float4*)&sm[W2K_O + 4 * i] = v;
    }
    if (tid < 8) {
        float s = g1[tid] * rs; sm[S1_O + tid] = s; sm[B1_O + tid] = c1b[tid] * s + b1[tid];
    } else if (tid >= 32 && tid < 48) {
        int c = tid - 32; float s = g2[c] * rs; sm[S2_O + c] = s; sm[B2_O + c] = c2b[c] * s + b2[c];
    } else if (tid >= 64 && tid < 96) {
        int c = tid - 64; float s = g3[c] * rs; sm[S3_O + c] = s; sm[B3_O + c] = c3b[c] * s + b3[c];
    }
    if (tid >= 128 && tid < 160) {
        int c = tid - 128;
        float p0 = pos[n * 3 + 0], p1 = pos[n * 3 + 1], p2 = pos[n * 3 + 2];
        float h = p0 * pw1[c] + p1 * pw1[32 + c] + p2 * pw1[64 + c] + pb1[c];
        sm[HID_O + c] = fmaxf(h, 0.f);
    }
    for (int i = tid; i < 1024; i += 256) sm[SXP_O + 12 + i] = x[(size_t)n * 1024 + i];
    if (tid < 12) { sm[SXP_O + tid] = 0.f; sm[SXP_O + 1036 + tid] = 0.f; }
    __syncthreads();

    if (tid < 32) {
        float s = pb2[tid];
#pragma unroll
        for (int j = 0; j < 32; j++) s += sm[HID_O + j] * pw2[j * 32 + tid];
        sm[PE_O + tid] = s;
    }

    // conv1 (1->8, K=25) + BN + relu, write bf16 h1b
    {
        const int t0 = tid * 4;
        union UU { float4 q[7]; u64b p[14]; float f[28]; } uu;
#pragma unroll
        for (int i = 0; i < 7; i++) uu.q[i] = *(const float4*)&sm[SXP_O + t0 + 4 * i];
        const u64b* w1e = (const u64b*)&sm[W1E_O];
        const u64b* w1o = (const u64b*)&sm[W1O_O];
#pragma unroll
        for (int c = 0; c < 8; c++) {
            u64b a0 = 0, a1 = 0, a2 = 0, a3 = 0;
#pragma unroll
            for (int m = 0; m < 12; m++) {
                u64b we = w1e[c * 12 + m];
                fma2(a0, we, uu.p[m]);
                fma2(a2, we, uu.p[m + 1]);
                u64b wo = w1o[c * 12 + m];
                fma2(a1, wo, uu.p[m + 1]);
                fma2(a3, wo, uu.p[m + 2]);
            }
            float w0 = sm[W1X_O + c], w24 = sm[W1X_O + 8 + c];
            float v0 = hsum2(a0) + w24 * uu.f[24];
            float v1 = hsum2(a1) + w0  * uu.f[1];
            float v2 = hsum2(a2) + w24 * uu.f[26];
            float v3 = hsum2(a3) + w0  * uu.f[3];
            float s = sm[S1_O + c], B = sm[B1_O + c];
            float o0 = fmaxf(v0 * s + B, 0.f);
            float o1 = fmaxf(v1 * s + B, 0.f);
            float o2 = fmaxf(v2 * s + B, 0.f);
            float o3 = fmaxf(v3 * s + B, 0.f);
            uint2 pk;
            pk.x = bf2pack(o0, o1);
            pk.y = bf2pack(o2, o3);
            *(uint2*)&smu[H1B_O + c * 514 + (t0 >> 1)] = pk;
        }
    }
    __syncthreads();

    // pool1: u1 (f32) from bf16 h1b
    for (int c = 0; c < 8; c++) {
        const unsigned* hb = &smu[H1B_O + c * 514];
        for (int j2 = tid; j2 < 510; j2 += 256) {
            unsigned a = hb[j2], b = hb[j2 + 1], d = hb[j2 + 2];
            float a0 = __uint_as_float(a << 16), a1 = __uint_as_float(a & 0xffff0000u);
            float b0 = __uint_as_float(b << 16), b1 = __uint_as_float(b & 0xffff0000u);
            float d0 = __uint_as_float(d << 16);
            float mid = a1 + b0 + b1;
            sm[U1_O + c * 1024 + 2 * j2]     = 0.25f * (a0 + mid);
            sm[U1_O + c * 1024 + 2 * j2 + 1] = 0.25f * (mid + d0);
        }
    }
    __syncthreads();

    // conv2 (8->16, K=15 padded 16) fused pool4 + BN + relu -> h2 (f32)
    {
        const int q = tid & 7, tpq = tid >> 3;
        u64b accL[8], accH[8];
#pragma unroll
        for (int it = 0; it < 8; it++) { accL[it] = 0; accH[it] = 0; }
#pragma unroll
        for (int ci = 0; ci < 8; ci++) {
            union WU { float4 v; u64b p[2]; } wv[8];
#pragma unroll
            for (int m = 0; m < 8; m++)
                wv[m].v = *(const float4*)&sm[W2K_O + 4 * ((ci * 8 + m) * 8 + q)];
#pragma unroll
            for (int it = 0; it < 8; it++) {
                int tp = tpq + 32 * it;
                if (tp < 252) {
                    union UB { float4 v[4]; u64b p[8]; } ub;
                    const float4* up = (const float4*)&sm[U1_O + ci * 1024 + 4 * tp];
#pragma unroll
                    for (int i = 0; i < 4; i++) ub.v[i] = up[i];
#pragma unroll
                    for (int m = 0; m < 8; m++) {
                        fma2(accL[it], wv[m].p[0], ub.p[m]);
                        fma2(accH[it], wv[m].p[1], ub.p[m]);
                    }
                }
            }
        }
        float sL = sm[S2_O + q], BL = sm[B2_O + q];
        float sH = sm[S2_O + q + 8], BH = sm[B2_O + q + 8];
#pragma unroll
        for (int it = 0; it < 8; it++) {
            int tp = tpq + 32 * it;
            if (tp < 252) {
                sm[H2_O + q * 253 + tp]       = fmaxf(hsum2(accL[it]) * sL + BL, 0.f);
                sm[H2_O + (q + 8) * 253 + tp] = fmaxf(hsum2(accH[it]) * sH + BH, 0.f);
            }
        }
    }
    __syncthreads();

    // pool2 (u2) + late load of conv3 weights into dead u1 space
    for (int i = tid; i < 1024; i += 256) {
        int ci = i >> 6, m = (i >> 4) & 3, q = i & 15;
        int base = q * 112 + ci * 7 + 2 * m;
        float4 v;
        v.x = c3w[base];
        v.y = (2 * m + 1 < 7) ? c3w[base + 1] : 0.f;
        v.z = c3w[base + 1792];
        v.w = (2 * m + 1 < 7) ? c3w[base + 1793] : 0.f;
        *(float4*)&sm[W3K_O + 4 * i] = v;
    }
    for (int j = tid; j < 16 * 248; j += 256) {
        int c = j / 248, jj = j % 248;
        const float* hr = &sm[H2_O + c * 253 + jj];
        sm[U2_O + c * 248 + jj] = 0.25f * (hr[0] + hr[1] + hr[2] + hr[3]);
    }
    __syncthreads();

    // conv3 (16->32, K=7 padded 8) fused pool4 + pe, write bf16 pre-scaled by dinv[n]
    {
        const int q = tid & 15, tpq = tid >> 4;
        u64b accL[4], accH[4];
#pragma unroll
        for (int it = 0; it < 4; it++) { accL[it] = 0; accH[it] = 0; }
#pragma unroll
        for (int ci = 0; ci < 16; ci++) {
            union WU { float4 v; u64b p[2]; } wv[4];
#pragma unroll
            for (int m = 0; m < 4; m++)
                wv[m].v = *(const float4*)&sm[W3K_O + 4 * ((ci * 4 + m) * 16 + q)];
#pragma unroll
            for (int it = 0; it < 4; it++) {
                int tp = tpq + 16 * it;
                if (tp < 61) {
                    union UB { float4 v[2]; u64b p[4]; } ub;
                    const float4* up = (const float4*)&sm[U2_O + ci * 248 + 4 * tp];
                    ub.v[0] = up[0]; ub.v[1] = up[1];
#pragma unroll
                    for (int m = 0; m < 4; m++) {
                        fma2(accL[it], wv[m].p[0], ub.p[m]);
                        fma2(accH[it], wv[m].p[1], ub.p[m]);
                    }
                }
            }
        }
        float sL = sm[S3_O + q], BL = sm[B3_O + q], peL = sm[PE_O + q];
        float sH = sm[S3_O + q + 16], BH = sm[B3_O + q + 16], peH = sm[PE_O + q + 16];
#pragma unroll
        for (int it = 0; it < 4; it++) {
            int tp = tpq + 16 * it;
            if (tp < 61) {
                size_t base = ((size_t)n * 61 + tp) * 32;
                out[base + q]      = __float2bfloat16((fmaxf(hsum2(accL[it]) * sL + BL, 0.f) + peL) * dvn);
                out[base + q + 16] = __float2bfloat16((fmaxf(hsum2(accH[it]) * sH + BH, 0.f) + peH) * dvn);
            }
        }
    }
}

// ---------------- fused GCN layer (2 nodes/block, M=128 tile) ----------------
// Input h pre-scaled by dinv[src]; gather is a pure sum.
template <int K, bool DO_CONTRIB>
__global__ __launch_bounds__(256, 2) void gcn_fused_kernel(
    const __nv_bfloat16* __restrict__ h, const float* __restrict__ W,
    const float* __restrict__ bias, __nv_bfloat16* __restrict__ out)
{
    constexpr int LDA = K + 8;
    constexpr int LDW = 136;
    constexpr int LDC = 132;
    constexpr int V8 = TP2 * K / 8;
    constexpr int VPT = (V8 + 255) / 256;
    extern __shared__ char sgc[];
    __nv_bfloat16* ws = (__nv_bfloat16*)sgc;
    __nv_bfloat16* as = ws + K * LDW;
    float* cs = (float*)sgc;
    __shared__ float bs[128];
    __shared__ float red[8][4];

    const int tid = threadIdx.x;
    const int bid = blockIdx.x;

    if (tid < 128) bs[tid] = bias[tid];
    for (int i = tid; i < K * 32; i += 256) {
        int k = i >> 5, c4 = i & 31;
        float4 v = *(const float4*)&W[k * 128 + c4 * 4];
        __nv_bfloat16* p = &ws[k * LDW + c4 * 4];
        p[0] = __float2bfloat16(v.x); p[1] = __float2bfloat16(v.y);
        p[2] = __float2bfloat16(v.z); p[3] = __float2bfloat16(v.w);
    }
    for (int i = tid; i < 6 * (K / 8); i += 256) {
        int r = 122 + i / (K / 8), c8 = i % (K / 8);
        *(uint4*)&as[r * LDA + c8 * 8] = make_uint4(0, 0, 0, 0);
    }

#pragma unroll 1
    for (int nh = 0; nh < 2; nh++) {
        const int n = 2 * bid + nh;
        const uint4* hn = (const uint4*)(h + (size_t)n * (TP2 * K));
        u64b accp[VPT][4];
#pragma unroll
        for (int v = 0; v < VPT; v++) {
            int i = tid + v * 256;
            if (i < V8) {
                uint4 b = hn[i];
                accp[v][0] = expand_bf2(b.x);
                accp[v][1] = expand_bf2(b.y);
                accp[v][2] = expand_bf2(b.z);
                accp[v][3] = expand_bf2(b.w);
            }
        }
        const int jb = g_off[n], je = g_off[n + 1];
        int e = jb;
        if (VPT == 1) {
            for (; e + 4 <= je; e += 4) {
                const uint4* p0 = (const uint4*)(h + (size_t)g_col[e]     * (TP2 * K));
                const uint4* p1 = (const uint4*)(h + (size_t)g_col[e + 1] * (TP2 * K));
                const uint4* p2 = (const uint4*)(h + (size_t)g_col[e + 2] * (TP2 * K));
                const uint4* p3 = (const uint4*)(h + (size_t)g_col[e + 3] * (TP2 * K));
                if (tid < V8) {
                    uint4 b0 = p0[tid], b1 = p1[tid], b2 = p2[tid], b3 = p3[tid];
                    acc_pair_u4(accp[0], b0, b1);
                    acc_pair_u4(accp[0], b2, b3);
                }
            }
        }
        for (; e + 2 <= je; e += 2) {
            const uint4* p0 = (const uint4*)(h + (size_t)g_col[e]     * (TP2 * K));
            const uint4* p1 = (const uint4*)(h + (size_t)g_col[e + 1] * (TP2 * K));
            uint4 b0[VPT], b1[VPT];
#pragma unroll
            for (int v = 0; v < VPT; v++) {
                int i = tid + v * 256;
                if (i < V8) { b0[v] = p0[i]; b1[v] = p1[i]; }
            }
#pragma unroll
            for (int v = 0; v < VPT; v++) {
                int i = tid + v * 256;
                if (i < V8) acc_pair_u4(accp[v], b0[v], b1[v]);
            }
        }
        if (e < je) {
            const uint4* p0 = (const uint4*)(h + (size_t)g_col[e] * (TP2 * K));
#pragma unroll
            for (int v = 0; v < VPT; v++) {
                int i = tid + v * 256;
                if (i < V8) acc_u4(accp[v], p0[i]);
            }
        }
#pragma unroll
        for (int v = 0; v < VPT; v++) {
            int i = tid + v * 256;
            if (i < V8) {
                int r = nh * TP2 + i / (K / 8), c8 = i % (K / 8);
                uint4 o;
                o.x = pair_to_bf2(accp[v][0]);
                o.y = pair_to_bf2(accp[v][1]);
                o.z = pair_to_bf2(accp[v][2]);
                o.w = pair_to_bf2(accp[v][3]);
                *(uint4*)&as[r * LDA + c8 * 8] = o;
            }
        }
    }
    __syncthreads();

    const int wid = tid >> 5;
    const int wr = wid & 3;
    const int wc = wid >> 2;
    wmma::fragment<wmma::accumulator, 16, 16, 16, float> cf[2][4];
#pragma unroll
    for (int i = 0; i < 2; i++)
#pragma unroll
        for (int j = 0; j < 4; j++) wmma::fill_fragment(cf[i][j], 0.f);

#pragma unroll
    for (int k0 = 0; k0 < K; k0 += 16) {
        wmma::fragment<wmma::matrix_a, 16, 16, 16, __nv_bfloat16, wmma::row_major> af[2];
#pragma unroll
        for (int i = 0; i < 2; i++)
            wmma::load_matrix_sync(af[i], as + (wr * 32 + i * 16) * LDA + k0, LDA);
        wmma::fragment<wmma::matrix_b, 16, 16, 16, __nv_bfloat16, wmma::row_major> bf[4];
#pragma unroll
        for (int j = 0; j < 4; j++)
            wmma::load_matrix_sync(bf[j], ws + k0 * LDW + wc * 64 + j * 16, LDW);
#pragma unroll
        for (int i = 0; i < 2; i++)
#pragma unroll
            for (int j = 0; j < 4; j++)
                wmma::mma_sync(cf[i][j], af[i], bf[j], cf[i][j]);
    }
    __syncthreads();
#pragma unroll
    for (int i = 0; i < 2; i++)
#pragma unroll
        for (int j = 0; j < 4; j++)
            wmma::store_matrix_sync(cs + (wr * 32 + i * 16) * LDC + wc * 64 + j * 16,
                                    cf[i][j], LDC, wmma::mem_row_major);
    __syncthreads();

    if (!DO_CONTRIB) {
        for (int idx = tid; idx < 128 * 64; idx += 256) {
            int r = idx >> 6, c2 = idx & 63;
            if (r < 122) {
                int nh = (r >= TP2) ? 1 : 0;
                int n = 2 * bid + nh;
                int t = r - TP2 * nh;
                float dv = g_dinv[n];
                float v0 = fmaxf(cs[r * LDC + 2 * c2]     * dv + bs[2 * c2], 0.f) * dv;
                float v1 = fmaxf(cs[r * LDC + 2 * c2 + 1] * dv + bs[2 * c2 + 1], 0.f) * dv;
                ((__nv_bfloat162*)out)[(size_t)(n * TP2 + t) * 64 + c2] =
                    __floats2bfloat162_rn(v0, v1);
            }
        }
    } else {
        // fused contrib with TRANSPOSED dw (coalesced: lanes = consecutive d)
        const int half = tid >> 7, d = tid & 127;
        const int n = 2 * bid + half;
        const float dv = g_dinv[n];
        const float bsv = bs[d];
        float a0 = 0.f, a1 = 0.f, a2 = 0.f, a3 = 0.f;
#pragma unroll 4
        for (int t = 0; t < TP2; t++) {
            float v = fmaxf(cs[(half * TP2 + t) * LDC + d] * dv + bsv, 0.f);
            const float4 w = *(const float4*)&g_dwt[(size_t)(t * DD + d) * 4];
            a0 += v * w.x; a1 += v * w.y; a2 += v * w.z; a3 += v * w.w;
        }
#pragma unroll
        for (int o = 16; o > 0; o >>= 1) {
            a0 += __shfl_down_sync(0xffffffff, a0, o);
            a1 += __shfl_down_sync(0xffffffff, a1, o);
            a2 += __shfl_down_sync(0xffffffff, a2, o);
            a3 += __shfl_down_sync(0xffffffff, a3, o);
        }
        const int wid2 = tid >> 5;
        if ((tid & 31) == 0) {
            red[wid2][0] = a0; red[wid2][1] = a1; red[wid2][2] = a2; red[wid2][3] = a3;
        }
        __syncthreads();
        if (tid < 8) {
            int hh = tid >> 2, j = tid & 3;
            float s = red[hh * 4 + 0][j] + red[hh * 4 + 1][j]
                    + red[hh * 4 + 2][j] + red[hh * 4 + 3][j];
            g_contrib[(2 * bid + hh) * 4 + j] = s;
        }
    }
}

// ---------------- batch pooling + bias + log_softmax ----------------
__global__ __launch_bounds__(256) void final_kernel(
    const int* __restrict__ batch, const float* __restrict__ db,
    float* __restrict__ out)
{
    const int b = blockIdx.x, tid = threadIdx.x;
    float a0 = 0.f, a1 = 0.f, a2 = 0.f, a3 = 0.f;
    int c = 0;
    for (int n = tid; n < NN; n += 256) {
        if (batch[n] == b) {
            const float4 v = *(const float4*)&g_contrib[n * 4];
            a0 += v.x; a1 += v.y; a2 += v.z; a3 += v.w;
            c++;
        }
    }
    __shared__ float r0[256], r1[256], r2[256], r3[256];
    __shared__ int rc[256];
    r0[tid] = a0; r1[tid] = a1; r2[tid] = a2; r3[tid] = a3; rc[tid] = c;
    __syncthreads();
    for (int s = 128; s > 0; s >>= 1) {
        if (tid < s) {
            r0[tid] += r0[tid + s]; r1[tid] += r1[tid + s];
            r2[tid] += r2[tid + s]; r3[tid] += r3[tid + s];
            rc[tid] += rc[tid + s];
        }
        __syncthreads();
    }
    if (tid == 0) {
        float cc = fmaxf((float)rc[0], 1.f);
        float l0 = r0[0] / cc + db[0];
        float l1 = r1[0] / cc + db[1];
        float l2 = r2[0] / cc + db[2];
        float l3 = r3[0] / cc + db[3];
        float m = fmaxf(fmaxf(l0, l1), fmaxf(l2, l3));
        float sum = expf(l0 - m) + expf(l1 - m) + expf(l2 - m) + expf(l3 - m);
        float ls = logf(sum);
        out[b * 4 + 0] = l0 - m - ls;
        out[b * 4 + 1] = l1 - m - ls;
        out[b * 4 + 2] = l2 - m - ls;
        out[b * 4 + 3] = l3 - m - ls;
    }
}

// ---------------- launch ----------------
extern "C" void kernel_launch(void* const* d_in, const int* in_sizes, int n_in,
                              void* d_out, int out_size)
{
    const float* x   = (const float*)d_in[0];
    const float* pos = (const float*)d_in[1];
    const float* c1w = (const float*)d_in[2];
    const float* c1b = (const float*)d_in[3];
    const float* bg1 = (const float*)d_in[4];
    const float* bb1 = (const float*)d_in[5];
    const float* c2w = (const float*)d_in[6];
    const float* c2b = (const float*)d_in[7];
    const float* bg2 = (const float*)d_in[8];
    const float* bb2 = (const float*)d_in[9];
    const float* c3w = (const float*)d_in[10];
    const float* c3b = (const float*)d_in[11];
    const float* bg3 = (const float*)d_in[12];
    const float* bb3 = (const float*)d_in[13];
    const float* pw1 = (const float*)d_in[14];
    const float* pb1 = (const float*)d_in[15];
    const float* pw2 = (const float*)d_in[16];
    const float* pb2 = (const float*)d_in[17];
    const float* gw1 = (const float*)d_in[18];
    const float* gb1 = (const float*)d_in[19];
    const float* gw2 = (const float*)d_in[20];
    const float* gb2 = (const float*)d_in[21];
    const float* dw  = (const float*)d_in[22];
    const float* db  = (const float*)d_in[23];
    const int*   ei  = (const int*)d_in[24];
    const int*   bat = (const int*)d_in[25];
    float* out = (float*)d_out;

    const int g1_smem = 128 * 132 * 4;                    // 67584 (C tile dominates)
    const int g2_smem = (128 * 136 + 128 * 136) * 2;      // 69632

    cudaFuncSetAttribute(conv_kernel, cudaFuncAttributeMaxDynamicSharedMemorySize, CONV_SMEM_BYTES);
    cudaFuncSetAttribute(gcn_fused_kernel<32, false>,  cudaFuncAttributeMaxDynamicSharedMemorySize, g1_smem);
    cudaFuncSetAttribute(gcn_fused_kernel<128, true>,  cudaFuncAttributeMaxDynamicSharedMemorySize, g2_smem);

    __nv_bfloat16 *h0, *h1;
    cudaGetSymbolAddress((void**)&h0, g_h0);
    cudaGetSymbolAddress((void**)&h1, g_h1);

    zero_cnt_kernel<<<8, 256>>>();
    count_kernel<<<64, 256>>>(ei);
    scan_kernel<<<1, 256>>>();
    fill_kernel<<<64, 256>>>(ei);
    dwt_kernel<<<(TP2 * DD + 255) / 256, 256>>>(dw);

    conv_kernel<<<NN, 256, CONV_SMEM_BYTES>>>(
        x, pos, c1w, c1b, bg1, bb1, c2w, c2b, bg2, bb2,
        c3w, c3b, bg3, bb3, pw1, pb1, pw2, pb2, h0);

    gcn_fused_kernel<32, false><<<NN / 2, 256, g1_smem>>>(h0, gw1, gb1, h1);
    gcn_fused_kernel<128, true><<<NN / 2, 256, g2_smem>>>(h1, gw2, gb2, nullptr);

    final_kernel<<<BBATCH, 256>>>(bat, db, out);
}